// round 14
// baseline (speedup 1.0000x reference)
#include <cuda_runtime.h>
#include <cuda_fp16.h>
#include <cstdint>
#include <math.h>

#define NH 8
#define NN 2048
#define BM 128
#define NTILE 32
#define PDT 68

typedef unsigned long long u64;

// ---------------- k_attn smem word-offsets ----------------
#define F_QHI  0          /* A-frags: 8w x 4ks x 32l x 4 = 4096 words each */
#define F_QLO  4096
#define F_THI  8192
#define F_TLO  12288
// per-buffer word offsets; rows stride 80 words (64 data + 16 pad, bank-exact)
#define O_K    0          /* 64 rows x 80 = 5120 */
#define O_H    5120
#define O_V    10240
#define BUFSZ  15360
#define BUF0   16384
#define BUF1   31744
#define O_MSK  47104      /* 64 ballot words */
#define O_CNT  47168      /* 8 warp popcounts */
#define SMEM_ATTN ((47176) * 4)   /* 188,704 B */

// ---------------- helpers ----------------
__device__ __forceinline__ void sp2(float xe, float xo, uint32_t& hi, uint32_t& lo) {
    const __half he = __float2half_rn(xe), ho = __float2half_rn(xo);
    const float re = xe - __half2float(he), ro = xo - __half2float(ho);
    const __half2 H = __halves2half2(he, ho);
    const __half2 L = __halves2half2(__float2half_rn(re), __float2half_rn(ro));
    hi = *(const uint32_t*)&H;
    lo = *(const uint32_t*)&L;
}
__device__ __forceinline__ void mma16(float c[4], uint32_t a0, uint32_t a1, uint32_t a2, uint32_t a3,
                                      uint32_t b0, uint32_t b1) {
    asm volatile(
        "mma.sync.aligned.m16n8k16.row.col.f32.f16.f16.f32 "
        "{%0,%1,%2,%3},{%4,%5,%6,%7},{%8,%9},{%0,%1,%2,%3};"
        : "+f"(c[0]), "+f"(c[1]), "+f"(c[2]), "+f"(c[3])
        : "r"(a0), "r"(a1), "r"(a2), "r"(a3), "r"(b0), "r"(b1));
}
__device__ __forceinline__ void cp16(uint32_t dst_smem, const void* src) {
    asm volatile("cp.async.cg.shared.global [%0], [%1], 16;" :: "r"(dst_smem), "l"(src));
}
#define CP_COMMIT() asm volatile("cp.async.commit_group;" ::: "memory")
#define CP_WAIT0()  asm volatile("cp.async.wait_group 0;" ::: "memory")

// -------- device scratch --------
// fragment-interleaved packed operands: uint4 = (hi_b0, hi_b1, lo_b0, lo_b1)
__device__ float g_S[NH * 64 * 64];
__device__ float g_T[NH * NN * 64];
__device__ uint4 g_Kp[NH * NN * 16];          // per (h, n): 16 quads (ks*4+lt)
__device__ uint4 g_Hp[NH * NN * 16];          // Khat, same layout
__device__ uint4 g_Vp[NH * NTILE * 64 * 16];  // per (h, tile, d): 16 quads
__device__ unsigned int g_cnt[NH];

// ============================================================
// Kernel A: S = softmax over flattened k*k of clusters @ clusters^T
// ============================================================
__global__ void k_clusterS(const float* __restrict__ clusters) {
    __shared__ float cl[64 * 64];
    __shared__ float ds[64 * 64];
    __shared__ float red[256];
    const int h = blockIdx.x, t = threadIdx.x;
    for (int i = t; i < 4096; i += 256) cl[i] = clusters[(size_t)h * 4096 + i];
    __syncthreads();
    float lmax = -1e30f;
    for (int i = t; i < 4096; i += 256) {
        const int kk = i >> 6, jj = i & 63;
        float s = 0.f;
#pragma unroll 16
        for (int d = 0; d < 64; d++) s += cl[kk * 64 + d] * cl[jj * 64 + d];
        ds[i] = s;
        lmax = fmaxf(lmax, s);
    }
    red[t] = lmax;
    __syncthreads();
    for (int o = 128; o > 0; o >>= 1) { if (t < o) red[t] = fmaxf(red[t], red[t + o]); __syncthreads(); }
    const float mx = red[0];
    __syncthreads();
    float lsum = 0.f;
    for (int i = t; i < 4096; i += 256) { const float e = expf(ds[i] - mx); ds[i] = e; lsum += e; }
    red[t] = lsum;
    __syncthreads();
    for (int o = 128; o > 0; o >>= 1) { if (t < o) red[t] += red[t + o]; __syncthreads(); }
    const float inv = 1.f / red[0];
    for (int i = t; i < 4096; i += 256) g_S[(size_t)h * 4096 + i] = ds[i] * inv;
    if (t == 0) g_cnt[h] = 0u;
}

// ============================================================
// Kernel P: pack K and V into fragment-interleaved quads.
// ============================================================
__global__ void __launch_bounds__(256) k_prep(const float* __restrict__ K,
                                              const float* __restrict__ V) {
    __shared__ float kt[64 * 64];
    __shared__ float vt[64 * 64];
    const int tile = blockIdx.x, h = blockIdx.y, t = threadIdx.x;
    const int c0 = tile * 64;
    const float* Ksrc = K + ((size_t)h * NN + c0) * 64;
    const float* Vsrc = V + ((size_t)h * NN + c0) * 64;
    for (int i = t; i < 4096; i += 256) { kt[i] = Ksrc[i]; vt[i] = Vsrc[i]; }
    __syncthreads();
    for (int wi = t; wi < 1024; wi += 256) {
        const int n = wi >> 4, ck = wi & 15, ks = ck >> 2, lt = ck & 3;
        const int d0 = 16 * ks + 2 * lt;
        uint32_t h0, l0, h1, l1;
        sp2(kt[n * 64 + d0], kt[n * 64 + d0 + 1], h0, l0);
        sp2(kt[n * 64 + d0 + 8], kt[n * 64 + d0 + 9], h1, l1);
        g_Kp[((size_t)(h * NN + c0 + n)) * 16 + ck] = make_uint4(h0, h1, l0, l1);
    }
    for (int wi = t; wi < 1024; wi += 256) {
        const int d = wi >> 4, ck = wi & 15, ks = ck >> 2, lt = ck & 3;
        const int j0 = 16 * ks + 2 * lt;
        uint32_t h0, l0, h1, l1;
        sp2(vt[j0 * 64 + d], vt[(j0 + 1) * 64 + d], h0, l0);
        sp2(vt[(j0 + 8) * 64 + d], vt[(j0 + 9) * 64 + d], h1, l1);
        g_Vp[((size_t)((h * NTILE + tile) * 64 + d)) * 16 + ck] = make_uint4(h0, h1, l0, l1);
    }
}

// ============================================================
// k-major 64^3 SIMT GEMM helper for k_projhat (exact fp32)
// ============================================================
__device__ __forceinline__ void gemmT(const float* __restrict__ AT, const float* __restrict__ WT,
                                      int i0, int o0, float out[16]) {
    float acc[16];
#pragma unroll
    for (int q = 0; q < 16; q++) acc[q] = 0.f;
#pragma unroll 8
    for (int k = 0; k < 64; k++) {
        const float4 a = *(const float4*)&AT[k * PDT + i0];
        const float4 w = *(const float4*)&WT[k * PDT + o0];
        const float av[4] = {a.x, a.y, a.z, a.w};
        const float wv[4] = {w.x, w.y, w.z, w.w};
#pragma unroll
        for (int ii = 0; ii < 4; ii++)
#pragma unroll
            for (int jj = 0; jj < 4; jj++) acc[ii * 4 + jj] += av[ii] * wv[jj];
    }
#pragma unroll
    for (int q = 0; q < 16; q++) out[q] = acc[q];
}

__global__ void __launch_bounds__(256) k_projhat(
    const float* __restrict__ Qin, const float* __restrict__ Kin,
    const float* __restrict__ clusters, const float* __restrict__ W1,
    const float* __restrict__ b1, const float* __restrict__ W2,
    const float* __restrict__ b2) {
    extern __shared__ float smb[];
    float* AT = smb;
    float* BT = smb + 64 * PDT;
    float* WT = smb + 2 * 64 * PDT;
    const int t = threadIdx.x;
    const int h = blockIdx.y;
    const int row0 = blockIdx.x * 64;
    const int isK = blockIdx.z;
    const int ti = t >> 4, tj = t & 15, i0 = ti * 4, o0 = tj * 4;
    const float* src = (isK ? Kin : Qin) + ((size_t)h * NN + row0) * 64;

    for (int i = t; i < 4096; i += 256) {
        AT[(i & 63) * PDT + (i >> 6)] = src[i];
        WT[(i >> 6) * PDT + (i & 63)] = W1[(i & 63) * 64 + (i >> 6)];
    }
    __syncthreads();

    float out[16];
    gemmT(AT, WT, i0, o0, out);
    __syncthreads();
#pragma unroll
    for (int jj = 0; jj < 4; jj++) {
        const float bb = b1[o0 + jj];
        *(float4*)&BT[(o0 + jj) * PDT + i0] = make_float4(
            fmaxf(out[0 * 4 + jj] + bb, 0.f), fmaxf(out[1 * 4 + jj] + bb, 0.f),
            fmaxf(out[2 * 4 + jj] + bb, 0.f), fmaxf(out[3 * 4 + jj] + bb, 0.f));
    }
    for (int i = t; i < 4096; i += 256)
        WT[(i >> 6) * PDT + (i & 63)] = W2[(i & 63) * 64 + (i >> 6)];
    __syncthreads();
    gemmT(BT, WT, i0, o0, out);
    __syncthreads();
#pragma unroll
    for (int jj = 0; jj < 4; jj++) {
        const float bb = b2[o0 + jj];
        *(float4*)&AT[(o0 + jj) * PDT + i0] = make_float4(
            out[0 * 4 + jj] + bb, out[1 * 4 + jj] + bb,
            out[2 * 4 + jj] + bb, out[3 * 4 + jj] + bb);
    }
    for (int i = t; i < 4096; i += 256)
        WT[(i >> 6) * PDT + (i & 63)] = clusters[(size_t)h * 4096 + (i & 63) * 64 + (i >> 6)];
    __syncthreads();
    gemmT(AT, WT, i0, o0, out);
#pragma unroll
    for (int q = 0; q < 16; q++) out[q] = 1.f / (1.f + expf(-out[q]));

    if (isK) {
        // Khat -> fragment-interleaved quads. Cols o0..o0+3 = pairs p0=2tj, p1=2tj+1.
#pragma unroll
        for (int ii = 0; ii < 4; ii++) {
            const int row = row0 + i0 + ii;
            uint32_t* wbase = (uint32_t*)&g_Hp[((size_t)(h * NN + row)) * 16];
            {
                const int p = 2 * tj, ks = p >> 3, r = p & 7, lt = r & 3, slot = r >> 2;
                uint32_t hi, lo;
                sp2(out[ii * 4 + 0], out[ii * 4 + 1], hi, lo);
                wbase[(ks * 4 + lt) * 4 + slot] = hi;
                wbase[(ks * 4 + lt) * 4 + slot + 2] = lo;
            }
            {
                const int p = 2 * tj + 1, ks = p >> 3, r = p & 7, lt = r & 3, slot = r >> 2;
                uint32_t hi, lo;
                sp2(out[ii * 4 + 2], out[ii * 4 + 3], hi, lo);
                wbase[(ks * 4 + lt) * 4 + slot] = hi;
                wbase[(ks * 4 + lt) * 4 + slot + 2] = lo;
            }
        }
    } else {
        __syncthreads();
#pragma unroll
        for (int jj = 0; jj < 4; jj++)
            *(float4*)&BT[(o0 + jj) * PDT + i0] = make_float4(
                out[0 * 4 + jj], out[1 * 4 + jj], out[2 * 4 + jj], out[3 * 4 + jj]);
        for (int i = t; i < 4096; i += 256)
            WT[(i >> 6) * PDT + (i & 63)] = g_S[(size_t)h * 4096 + i];
        __syncthreads();
        gemmT(BT, WT, i0, o0, out);
#pragma unroll
        for (int ii = 0; ii < 4; ii++)
            *(float4*)&g_T[((size_t)h * NN + row0 + i0 + ii) * 64 + o0] =
                make_float4(out[ii * 4 + 0], out[ii * 4 + 1], out[ii * 4 + 2], out[ii * 4 + 3]);
    }
}

// ============================================================
// Kernel C: fused attention, fp16 m16n8k16 hi/lo splits.
// Fragment-interleaved B operands: one LDS.128 = full hi/lo frag pair.
// Double-buffered cp.async tiles; E stays in registers.
// ============================================================
__global__ void __launch_bounds__(256) k_attn(
    const float* __restrict__ Qg, const int* __restrict__ maskg,
    const float* __restrict__ ug, float* __restrict__ Xout) {
    extern __shared__ float sf[];
    uint32_t* su = (uint32_t*)sf;
    const uint32_t sb4 = (uint32_t)__cvta_generic_to_shared(sf);
    const int t = threadIdx.x, l = t & 31, w = t >> 5;
    const int lg = l >> 2, lt = l & 3;
    const int h = blockIdx.y, row0 = blockIdx.x * BM;

    // ---- prologue 1: Q and T A-fragments (fp16 hi/lo), fragment-major ----
    {
        const float* Qs = Qg + ((size_t)h * NN + row0) * 64;
        const float* Ts = g_T + ((size_t)h * NN + row0) * 64;
        for (int ks = 0; ks < 4; ks++) {
#pragma unroll
            for (int i = 0; i < 4; i++) {
                const int row = 16 * w + lg + 8 * (i & 1);
                const int col = 16 * ks + 2 * lt + 8 * (i >> 1);
                const int fi = ((w * 4 + ks) * 32 + l) * 4 + i;
                const float2 q = *(const float2*)&Qs[row * 64 + col];
                sp2(q.x, q.y, su[F_QHI + fi], su[F_QLO + fi]);
                const float2 tv = *(const float2*)&Ts[row * 64 + col];
                sp2(tv.x, tv.y, su[F_THI + fi], su[F_TLO + fi]);
            }
        }
    }

    // ---- prologue 2: whole-mask ballots ----
    for (int g = 0; g < 8; g++) {
        const unsigned bal = __ballot_sync(0xffffffffu, maskg[g * 256 + t] != 0);
        if (l == 0) su[O_MSK + g * 8 + w] = bal;
    }

    // ---- prologue 3: cp.async tile 0 into BUF0 ----
    {
        const uint32_t bbb = sb4 + BUF0 * 4;
#pragma unroll
        for (int r = 0; r < 4; r++) {
            const int wi = t + r * 256;
            const int n = wi >> 4, ck = wi & 15;
            const uint32_t doff = (n * 80 + ck * 4) * 4;
            cp16(bbb + O_K * 4 + doff, g_Kp + (size_t)(h * NN + n) * 16 + ck);
            cp16(bbb + O_H * 4 + doff, g_Hp + (size_t)(h * NN + n) * 16 + ck);
            cp16(bbb + O_V * 4 + doff, g_Vp + (size_t)(h * NTILE * 64 + n) * 16 + ck);
        }
        CP_COMMIT();
        CP_WAIT0();
    }
    __syncthreads();

    float Co[8][4];
#pragma unroll
    for (int nt = 0; nt < 8; nt++)
#pragma unroll
        for (int q = 0; q < 4; q++) Co[nt][q] = 0.f;
    float Lp0 = 0.f, Lp1 = 0.f;
    unsigned cnt = 0;
    const int gr0 = row0 + 16 * w + lg, gr1 = gr0 + 8;
    const float* u0p = ug + ((size_t)h * NN + gr0) * NN;
    const float* u1p = ug + ((size_t)h * NN + gr1) * NN;

    for (int tile = 0; tile < NTILE; tile++) {
        const int c0 = tile * 64;
        const int bb = (tile & 1) ? BUF1 : BUF0;
        const int nb = (tile & 1) ? BUF0 : BUF1;

        // ---- issue next tile's cp.async ----
        if (tile + 1 < NTILE) {
            const int c1 = c0 + 64;
            const uint32_t nbb = sb4 + nb * 4;
#pragma unroll
            for (int r = 0; r < 4; r++) {
                const int wi = t + r * 256;
                const int n = wi >> 4, ck = wi & 15;
                const uint32_t doff = (n * 80 + ck * 4) * 4;
                cp16(nbb + O_K * 4 + doff, g_Kp + (size_t)(h * NN + c1 + n) * 16 + ck);
                cp16(nbb + O_H * 4 + doff, g_Hp + (size_t)(h * NN + c1 + n) * 16 + ck);
                cp16(nbb + O_V * 4 + doff, g_Vp + (size_t)((h * NTILE + tile + 1) * 64 + n) * 16 + ck);
            }
            CP_COMMIT();
        }

        // ---- prefetch u ----
        float2 ua[8], ub[8];
#pragma unroll
        for (int nt = 0; nt < 8; nt++) {
            const int jc = c0 + nt * 8 + 2 * lt;
            ua[nt] = *(const float2*)&u0p[jc];
            ub[nt] = *(const float2*)&u1p[jc];
        }

        // ---- S = QK^T (3 products), EA = T Khat^T (4 products) ----
        float Cs[8][4], Ce[8][4];
#pragma unroll
        for (int nt = 0; nt < 8; nt++)
#pragma unroll
            for (int q = 0; q < 4; q++) { Cs[nt][q] = 0.f; Ce[nt][q] = 0.f; }

        for (int ks = 0; ks < 4; ks++) {
            const int fb = ((w * 4 + ks) * 32 + l) * 4;
            const uint4 qh = *(const uint4*)&su[F_QHI + fb];
            const uint4 ql = *(const uint4*)&su[F_QLO + fb];
            const uint4 th = *(const uint4*)&su[F_THI + fb];
            const uint4 tl = *(const uint4*)&su[F_TLO + fb];
#pragma unroll
            for (int hf = 0; hf < 2; hf++) {
                uint4 kq[4], hq[4];
#pragma unroll
                for (int n = 0; n < 4; n++) {
                    const int base = bb + ((hf * 4 + n) * 8 + lg) * 80 + ks * 16 + lt * 4;
                    kq[n] = *(const uint4*)&su[O_K + base];
                    hq[n] = *(const uint4*)&su[O_H + base];
                }
                float* CsH = &Cs[hf * 4][0];
                float* CeH = &Ce[hf * 4][0];
#pragma unroll
                for (int n = 0; n < 4; n++) mma16(&CsH[n * 4], qh.x, qh.y, qh.z, qh.w, kq[n].x, kq[n].y);
#pragma unroll
                for (int n = 0; n < 4; n++) mma16(&CeH[n * 4], th.x, th.y, th.z, th.w, hq[n].x, hq[n].y);
#pragma unroll
                for (int n = 0; n < 4; n++) mma16(&CsH[n * 4], qh.x, qh.y, qh.z, qh.w, kq[n].z, kq[n].w);
#pragma unroll
                for (int n = 0; n < 4; n++) mma16(&CeH[n * 4], th.x, th.y, th.z, th.w, hq[n].z, hq[n].w);
#pragma unroll
                for (int n = 0; n < 4; n++) mma16(&CsH[n * 4], ql.x, ql.y, ql.z, ql.w, kq[n].x, kq[n].y);
#pragma unroll
                for (int n = 0; n < 4; n++) mma16(&CeH[n * 4], tl.x, tl.y, tl.z, tl.w, hq[n].x, hq[n].y);
#pragma unroll
                for (int n = 0; n < 4; n++) mma16(&CeH[n * 4], tl.x, tl.y, tl.z, tl.w, hq[n].z, hq[n].w);
            }
        }

        // ---- graph bit + exp; pack E into fp16 hi/lo A-frag pairs ----
        const u64 mall = (u64)su[O_MSK + 2 * tile] | ((u64)su[O_MSK + 2 * tile + 1] << 32);
        uint32_t ehi[8][2], elo[8][2];
#pragma unroll
        for (int nt = 0; nt < 8; nt++) {
            const int jc = nt * 8 + 2 * lt;
            const int mA = (int)((mall >> jc) & 1u), mB = (int)((mall >> (jc + 1)) & 1u);
            const unsigned g0 = (ua[nt].x < Ce[nt][0]) ? 1u : 0u;
            const unsigned g1 = (ua[nt].y < Ce[nt][1]) ? 1u : 0u;
            const unsigned g2 = (ub[nt].x < Ce[nt][2]) ? 1u : 0u;
            const unsigned g3 = (ub[nt].y < Ce[nt][3]) ? 1u : 0u;
            cnt += g0 + g1 + g2 + g3;
            const float e0 = (g0 && mA) ? __expf(Cs[nt][0] * 0.125f) : 0.f;
            const float e1 = (g1 && mB) ? __expf(Cs[nt][1] * 0.125f) : 0.f;
            const float e2 = (g2 && mA) ? __expf(Cs[nt][2] * 0.125f) : 0.f;
            const float e3 = (g3 && mB) ? __expf(Cs[nt][3] * 0.125f) : 0.f;
            Lp0 += e0 + e1;
            Lp1 += e2 + e3;
            sp2(e0, e1, ehi[nt][0], elo[nt][0]);
            sp2(e2, e3, ehi[nt][1], elo[nt][1]);
        }

        // ---- PV: O += E @ V (3 products) ----
        for (int ks = 0; ks < 4; ks++) {
            const uint32_t ah0 = ehi[2 * ks][0], ah1 = ehi[2 * ks][1];
            const uint32_t ah2 = ehi[2 * ks + 1][0], ah3 = ehi[2 * ks + 1][1];
            const uint32_t al0 = elo[2 * ks][0], al1 = elo[2 * ks][1];
            const uint32_t al2 = elo[2 * ks + 1][0], al3 = elo[2 * ks + 1][1];
#pragma unroll
            for (int hf = 0; hf < 2; hf++) {
                uint4 vq[4];
#pragma unroll
                for (int n = 0; n < 4; n++)
                    vq[n] = *(const uint4*)&su[O_V + bb + ((hf * 4 + n) * 8 + lg) * 80 + ks * 16 + lt * 4];
                float* CoH = &Co[hf * 4][0];
#pragma unroll
                for (int n = 0; n < 4; n++) mma16(&CoH[n * 4], ah0, ah1, ah2, ah3, vq[n].x, vq[n].y);
#pragma unroll
                for (int n = 0; n < 4; n++) mma16(&CoH[n * 4], ah0, ah1, ah2, ah3, vq[n].z, vq[n].w);
#pragma unroll
                for (int n = 0; n < 4; n++) mma16(&CoH[n * 4], al0, al1, al2, al3, vq[n].x, vq[n].y);
            }
        }

        if (tile + 1 < NTILE) CP_WAIT0();
        __syncthreads();
    }

    // ---- epilogue ----
    Lp0 += __shfl_xor_sync(0xffffffffu, Lp0, 1);
    Lp0 += __shfl_xor_sync(0xffffffffu, Lp0, 2);
    Lp1 += __shfl_xor_sync(0xffffffffu, Lp1, 1);
    Lp1 += __shfl_xor_sync(0xffffffffu, Lp1, 2);
    const float r0 = (Lp0 > 0.f) ? (1.f / Lp0) : 0.f;
    const float r1 = (Lp1 > 0.f) ? (1.f / Lp1) : 0.f;
    float* X0 = Xout + ((size_t)h * NN + gr0) * 64;
    float* X1 = Xout + ((size_t)h * NN + gr1) * 64;
#pragma unroll
    for (int nt = 0; nt < 8; nt++) {
        const int jc = nt * 8 + 2 * lt;
        *(float2*)&X0[jc] = make_float2(Co[nt][0] * r0, Co[nt][1] * r0);
        *(float2*)&X1[jc] = make_float2(Co[nt][2] * r1, Co[nt][3] * r1);
    }

    // ---- sparsity popcount ----
#pragma unroll
    for (int off = 16; off > 0; off >>= 1) cnt += __shfl_xor_sync(0xffffffffu, cnt, off);
    if (l == 0) su[O_CNT + w] = cnt;
    __syncthreads();
    if (t == 0) {
        unsigned tot = 0;
#pragma unroll
        for (int i = 0; i < 8; i++) tot += su[O_CNT + i];
        atomicAdd(&g_cnt[h], tot);
    }
}

// ============================================================
__global__ void k_spars(float* __restrict__ out) {
    const int h = threadIdx.x;
    if (h < NH) out[h] = (float)g_cnt[h] * (1.0f / ((float)NN * (float)NN));
}

// ============================================================
extern "C" void kernel_launch(void* const* d_in, const int* in_sizes, int n_in,
                              void* d_out, int out_size) {
    (void)in_sizes; (void)n_in;
    const float* Q        = (const float*)d_in[0];
    const float* K        = (const float*)d_in[1];
    const float* V        = (const float*)d_in[2];
    const int*   mask     = (const int*)d_in[3];
    const float* u        = (const float*)d_in[4];
    const float* clusters = (const float*)d_in[5];
    const float* W1       = (const float*)d_in[6];
    const float* b1       = (const float*)d_in[7];
    const float* W2       = (const float*)d_in[8];
    const float* b2       = (const float*)d_in[9];
    float* X = (float*)d_out;
    float* spars = X + (out_size - NH);

    const int SMB = 3 * 64 * PDT * 4;
    cudaFuncSetAttribute(k_projhat, cudaFuncAttributeMaxDynamicSharedMemorySize, SMB);
    cudaFuncSetAttribute(k_attn, cudaFuncAttributeMaxDynamicSharedMemorySize, SMEM_ATTN);

    k_clusterS<<<NH, 256>>>(clusters);
    k_prep<<<dim3(NTILE, NH), 256>>>(K, V);
    k_projhat<<<dim3(NN / 64, NH, 2), 256, SMB>>>(Q, K, clusters, W1, b1, W2, b2);
    k_attn<<<dim3(NN / BM, NH), 256, SMEM_ATTN>>>(Q, mask, u, X);
    k_spars<<<1, NH>>>(spars);
}